// round 11
// baseline (speedup 1.0000x reference)
#include <cuda_runtime.h>
#include <math.h>

#define T_STEPS 512
#define BATCH   256
#define IN_DIM  256
#define HID     1024
#define GH      (BATCH * HID)
#define NCTAS   128
#define RTHREADS 512             // recurrence threads (16 warps -> 4/SMSP)

#define SROW     40              // padded smem row (u32): conflict-free, LDS.64-friendly
#define HCHUNK   (64 * SROW)     // h chunk: 64 rows x 32 k (permuted)
#define WCHUNK   (128 * SROW)    // Whh chunk: 128 rows x 32 k (permuted)
#define TILEPART (64 * 128)      // one CTA's partial tile

// Persistent device state
__device__ float    g_partial[NCTAS * TILEPART];  // 4 MB split-K partials
__device__ unsigned g_h[GH];                      // tf32 h_t (k-permuted)
// Group barriers: one 128B line each: [0]=count, [16]=phase. Zero-init;
// count self-resets, phase is monotonic -> graph-replay safe.
__device__ unsigned g_tbar[32 * 32];              // per-tile (4-CTA) barriers
__device__ unsigned g_mbar[4 * 32];               // per-mt  (32-CTA) barriers

__device__ __forceinline__ unsigned f2tf(float f) {
    unsigned u;
    asm("cvt.rna.tf32.f32 %0, %1;" : "=r"(u) : "f"(f));
    return u;
}

__device__ __forceinline__ void mma8(float c[4], const unsigned a[4], const unsigned b[2]) {
    asm volatile(
        "mma.sync.aligned.m16n8k8.row.col.f32.tf32.tf32.f32 "
        "{%0,%1,%2,%3}, {%4,%5,%6,%7}, {%8,%9}, {%0,%1,%2,%3};\n"
        : "+f"(c[0]), "+f"(c[1]), "+f"(c[2]), "+f"(c[3])
        : "r"(a[0]), "r"(a[1]), "r"(a[2]), "r"(a[3]), "r"(b[0]), "r"(b[1]));
}

__device__ __forceinline__ void cp_cg16(unsigned* smem_dst, const unsigned* gmem_src) {
    unsigned s = (unsigned)__cvta_generic_to_shared(smem_dst);
    asm volatile("cp.async.cg.shared.global [%0], [%1], 16;\n" :: "r"(s), "l"(gmem_src));
}
#define CP_COMMIT() asm volatile("cp.async.commit_group;\n")

__device__ __forceinline__ float tanh_fast(float x) {
    float e = __expf(2.0f * x);
    return 1.0f - __fdividef(2.0f, e + 1.0f);
}

// ---------------------------------------------------------------------------
// Kernel 0: g_h = tf32(h0), k-permuted [k0,k4,k1,k5,k2,k6,k3,k7].
// ---------------------------------------------------------------------------
__global__ void init_h_kernel(const float* __restrict__ h0) {
    int i = blockIdx.x * blockDim.x + threadIdx.x;   // over 65536 float4
    int row = i >> 8;
    int c0  = (i & 255) * 4;
    const float4 v = *reinterpret_cast<const float4*>(h0 + (size_t)row * HID + c0);
    int base = (c0 & ~7) + ((c0 & 4) ? 1 : 0);
    unsigned* dst = g_h + (size_t)row * HID + base;
    dst[0] = f2tf(v.x); dst[2] = f2tf(v.y); dst[4] = f2tf(v.z); dst[6] = f2tf(v.w);
}

// ---------------------------------------------------------------------------
// Precompute (proven path, unchanged): Xpre = input @ Wih^T + bias -> d_out
// ---------------------------------------------------------------------------
__device__ __forceinline__ void fetch_tile(const float* __restrict__ g, int ld,
                                           int row0, int col0, float4* v) {
    int f = threadIdx.x;
    #pragma unroll
    for (int it = 0; it < 4; it++, f += 256) {
        int r = f >> 3, c4 = (f & 7) << 2;
        v[it] = *reinterpret_cast<const float4*>(g + (size_t)(row0 + r) * ld + col0 + c4);
    }
}
__device__ __forceinline__ void store_tile(const float4* v, unsigned* s) {
    int f = threadIdx.x;
    #pragma unroll
    for (int it = 0; it < 4; it++, f += 256) {
        int r = f >> 3, c4 = (f & 7) << 2;
        uint4 w;
        w.x = f2tf(v[it].x); w.y = f2tf(v[it].y); w.z = f2tf(v[it].z); w.w = f2tf(v[it].w);
        *reinterpret_cast<uint4*>(s + r * SROW + c4) = w;
    }
}
__device__ __forceinline__ void mma_block_pre(float c[4][4][4],
                                              const unsigned* As, const unsigned* Bs,
                                              int wm, int wn, int g, int tig) {
    #pragma unroll
    for (int ks = 0; ks < 4; ks++) {
        const int k8 = ks * 8;
        unsigned a[4][4], b[4][2];
        #pragma unroll
        for (int mi = 0; mi < 4; mi++) {
            const unsigned* p = As + (wm * 64 + mi * 16 + g) * SROW + k8 + tig;
            a[mi][0] = p[0]; a[mi][1] = p[8 * SROW]; a[mi][2] = p[4]; a[mi][3] = p[8 * SROW + 4];
        }
        #pragma unroll
        for (int ni = 0; ni < 4; ni++) {
            const unsigned* p = Bs + (wn * 32 + ni * 8 + g) * SROW + k8 + tig;
            b[ni][0] = p[0]; b[ni][1] = p[4];
        }
        #pragma unroll
        for (int mi = 0; mi < 4; mi++)
            #pragma unroll
            for (int ni = 0; ni < 4; ni++)
                mma8(c[mi][ni], a[mi], b[ni]);
    }
}

__global__ void __launch_bounds__(256, 1)
precompute_kernel(const float* __restrict__ input, const float* __restrict__ Wih,
                  const float* __restrict__ bias, float* __restrict__ out) {
    __shared__ unsigned As[128 * SROW];
    __shared__ unsigned Bs[128 * SROW];

    const int m0 = blockIdx.y * 128;
    const int n0 = blockIdx.x * 128;
    const int warp = threadIdx.x >> 5, lane = threadIdx.x & 31;
    const int wm = warp >> 2, wn = warp & 3, g = lane >> 2, tig = lane & 3;

    float c[4][4][4];
    #pragma unroll
    for (int i = 0; i < 4; i++)
        #pragma unroll
        for (int j = 0; j < 4; j++)
            #pragma unroll
            for (int k = 0; k < 4; k++) c[i][j][k] = 0.f;

    float4 pa[4], pb[4];
    fetch_tile(input, IN_DIM, m0, 0, pa);
    fetch_tile(Wih,   IN_DIM, n0, 0, pb);

    for (int kc = 0; kc < IN_DIM; kc += 32) {
        store_tile(pa, As);
        store_tile(pb, Bs);
        __syncthreads();
        if (kc + 32 < IN_DIM) {
            fetch_tile(input, IN_DIM, m0, kc + 32, pa);
            fetch_tile(Wih,   IN_DIM, n0, kc + 32, pb);
        }
        mma_block_pre(c, As, Bs, wm, wn, g, tig);
        __syncthreads();
    }

    #pragma unroll
    for (int mi = 0; mi < 4; mi++) {
        const int row = m0 + wm * 64 + mi * 16 + g;
        #pragma unroll
        for (int ni = 0; ni < 4; ni++) {
            const int col = n0 + wn * 32 + ni * 8 + 2 * tig;
            const float b0 = bias[col], b1 = bias[col + 1];
            float2 v0 = make_float2(c[mi][ni][0] + b0, c[mi][ni][1] + b1);
            float2 v1 = make_float2(c[mi][ni][2] + b0, c[mi][ni][3] + b1);
            *reinterpret_cast<float2*>(out + (size_t)row * HID + col)       = v0;
            *reinterpret_cast<float2*>(out + (size_t)(row + 8) * HID + col) = v1;
        }
    }
}

// ---------------------------------------------------------------------------
// Group barrier: PROVEN atomic pattern, scoped to n CTAs. Graph-replay safe.
// ---------------------------------------------------------------------------
__device__ __forceinline__ void group_barrier(unsigned* bar, unsigned n) {
    unsigned* cnt   = bar;
    unsigned* phase = bar + 16;
    __threadfence();
    __syncthreads();
    if (threadIdx.x == 0) {
        const unsigned ph = *(volatile unsigned*)phase;
        if (atomicAdd(cnt, 1u) == n - 1) {
            atomicExch(cnt, 0u);
            __threadfence();
            atomicAdd(phase, 1u);
        } else {
            while (*(volatile unsigned*)phase == ph) { }
        }
        __threadfence();
    }
    __syncthreads();
}

// ---------------------------------------------------------------------------
// Recurrence: 128 CTAs = 32 tiles (M64 x N128) x split-K-4, 512 threads/CTA
// (16 warps, warp tile m16 x n32 -> 4 warps/SMSP for latency hiding).
// ---------------------------------------------------------------------------
__device__ __forceinline__ void issue_h(unsigned* hb, const unsigned* ghsrc, int kb) {
    unsigned* dst = hb + (kb & 3) * HCHUNK;
    const unsigned* src = ghsrc + kb * 32;
    const int e = threadIdx.x;           // exactly 512 float4s per chunk
    const int r = e >> 3, g4 = (e & 7) * 4;
    cp_cg16(dst + r * SROW + g4, src + (size_t)r * HID + g4);
}

// warp tile m16 x n32: c[4][4] (4 n-blocks of n8)
__device__ __forceinline__ void mma_chunk(float c[4][4],
                                          const unsigned* As, const unsigned* Bs,
                                          int wm, int wn, int g, int tig) {
    #pragma unroll
    for (int ks = 0; ks < 4; ks++) {
        const int ko = ks * 8 + 2 * tig;   // permuted: (k_tig, k_tig+4) adjacent
        const unsigned* pa = As + (wm * 16 + g) * SROW + ko;
        uint2 alo = *reinterpret_cast<const uint2*>(pa);
        uint2 ahi = *reinterpret_cast<const uint2*>(pa + 8 * SROW);
        unsigned a[4] = {alo.x, ahi.x, alo.y, ahi.y};
        #pragma unroll
        for (int ni = 0; ni < 4; ni++) {
            uint2 bb = *reinterpret_cast<const uint2*>(Bs + (wn * 32 + ni * 8 + g) * SROW + ko);
            unsigned b2[2] = {bb.x, bb.y};
            mma8(c[ni], a, b2);
        }
    }
}

__global__ void __launch_bounds__(RTHREADS, 1)
recurrence_kernel(const float* __restrict__ h0, const float* __restrict__ Whh,
                  float* __restrict__ out, int write_tail) {
    extern __shared__ unsigned smem[];
    unsigned* whh  = smem;                // 8 * WCHUNK (resident, permuted tf32)
    unsigned* hbuf = smem + 8 * WCHUNK;   // 4 * HCHUNK ring

    const int cta  = blockIdx.x;          // 0..127
    const int tile = cta >> 2;            // 0..31
    const int sub  = cta & 3;             // K-split
    const int mt   = tile >> 3;           // 0..3   (64-row batch block)
    const int nt   = tile & 7;            // 0..7   (128-col hidden block)
    const int m0   = mt * 64;
    const int n0   = nt * 128;
    const int kc0  = sub * 256;

    const int warp = threadIdx.x >> 5;    // 0..15
    const int lane = threadIdx.x & 31;
    const int wm = warp & 3, wn = warp >> 2;     // 4 x 4 warp grid
    const int g = lane >> 2, tig = lane & 3;

    unsigned* tbar = &g_tbar[tile * 32];  // 4-CTA barrier (this tile's subs)
    unsigned* mbar = &g_mbar[mt * 32];    // 32-CTA barrier (this mt group)

    // One-time: resident Whh slice [n0..n0+128) x [kc0..kc0+256) -> permuted tf32
    #pragma unroll
    for (int kb = 0; kb < 8; kb++) {
        unsigned* ws = whh + kb * WCHUNK;
        int e = threadIdx.x;
        #pragma unroll
        for (int it = 0; it < 2; it++, e += RTHREADS) {   // 1024 float4s per chunk
            int r = e >> 3, c4 = (e & 7) * 4;
            const float4 v = *reinterpret_cast<const float4*>(
                Whh + (size_t)(n0 + r) * HID + kc0 + kb * 32 + c4);
            int base = (c4 & ~7) + ((c4 & 4) ? 1 : 0);
            ws[r * SROW + base + 0] = f2tf(v.x);
            ws[r * SROW + base + 2] = f2tf(v.y);
            ws[r * SROW + base + 4] = f2tf(v.z);
            ws[r * SROW + base + 6] = f2tf(v.w);
        }
    }

    // Phase-B partition is CTA-stationary: 512 threads cover 16 rows x 128 cols.
    const int ml   = threadIdx.x >> 5;            // 0..15
    const int c4b  = (threadIdx.x & 31) * 4;      // 0..124
    const int rowB = m0 + sub * 16 + ml;
    const int colB = n0 + c4b;
    float4 hreg = *reinterpret_cast<const float4*>(h0 + (size_t)rowB * HID + colB);

    const unsigned* ghsrc = g_h + (size_t)m0 * HID + kc0;
    float* myPart = g_partial + (size_t)cta * TILEPART;

    for (int t = 0; t < T_STEPS; t++) {
        // ---- Phase A: pipelined split-K GEMM over kc0..kc0+256 ----
        issue_h(hbuf, ghsrc, 0); CP_COMMIT();
        issue_h(hbuf, ghsrc, 1); CP_COMMIT();
        issue_h(hbuf, ghsrc, 2); CP_COMMIT();

        float c[4][4];
        #pragma unroll
        for (int j = 0; j < 4; j++)
            #pragma unroll
            for (int k = 0; k < 4; k++) c[j][k] = 0.f;

#define STEP_KB(KB, WN)                                                      \
        asm volatile("cp.async.wait_group %0;\n" :: "n"(WN));                \
        __syncthreads();                                                     \
        if ((KB) + 3 < 8) { issue_h(hbuf, ghsrc, (KB) + 3); CP_COMMIT(); }   \
        mma_chunk(c, hbuf + ((KB) & 3) * HCHUNK, whh + (KB) * WCHUNK, wm, wn, g, tig);

        STEP_KB(0, 2) STEP_KB(1, 2) STEP_KB(2, 2) STEP_KB(3, 2)
        STEP_KB(4, 2) STEP_KB(5, 2) STEP_KB(6, 1) STEP_KB(7, 0)
#undef STEP_KB

        // store partial tile (warp tile m16 x n32)
        {
            const int lr = wm * 16 + g;
            #pragma unroll
            for (int ni = 0; ni < 4; ni++) {
                const int lc = wn * 32 + ni * 8 + 2 * tig;
                *reinterpret_cast<float2*>(myPart + lr * 128 + lc) =
                    make_float2(c[ni][0], c[ni][1]);
                *reinterpret_cast<float2*>(myPart + (lr + 8) * 128 + lc) =
                    make_float2(c[ni][2], c[ni][3]);
            }
        }

        // ---- Xpre prefetch: own exclusive out[t] region; overlaps barrier ----
        float* dst = out + (size_t)t * GH;
        float4 xreg = __ldcg(reinterpret_cast<const float4*>(
            dst + (size_t)rowB * HID + colB));

        group_barrier(tbar, 4);   // tile group: partials ready

        // ---- Phase B: reduce 4 partials + Xpre -> tanh -> EMA -> out, g_h ----
        {
            const float* pb = g_partial + (size_t)(tile * 4) * TILEPART;
            const int lr = sub * 16 + ml;

            float4 acc = xreg;
            #pragma unroll
            for (int s = 0; s < 4; s++) {
                const float4 p = __ldcg(reinterpret_cast<const float4*>(
                    pb + (size_t)s * TILEPART + lr * 128 + c4b));
                acc.x += p.x; acc.y += p.y; acc.z += p.z; acc.w += p.w;
            }
            float4 r;
            r.x = fmaf(0.9f, hreg.x, 0.1f * tanh_fast(acc.x));
            r.y = fmaf(0.9f, hreg.y, 0.1f * tanh_fast(acc.y));
            r.z = fmaf(0.9f, hreg.z, 0.1f * tanh_fast(acc.z));
            r.w = fmaf(0.9f, hreg.w, 0.1f * tanh_fast(acc.w));
            hreg = r;
            *reinterpret_cast<float4*>(dst + (size_t)rowB * HID + colB) = r;

            const int base = (colB & ~7) + ((colB & 4) ? 1 : 0);
            unsigned* gp = g_h + (size_t)rowB * HID + base;
            gp[0] = f2tf(r.x); gp[2] = f2tf(r.y); gp[4] = f2tf(r.z); gp[6] = f2tf(r.w);

            if (write_tail && t == T_STEPS - 1) {
                *reinterpret_cast<float4*>(
                    out + (size_t)T_STEPS * GH + (size_t)rowB * HID + colB) = r;
            }
        }

        group_barrier(mbar, 32);  // mt group: h rows ready + partials reusable
    }
}

extern "C" void kernel_launch(void* const* d_in, const int* in_sizes, int n_in,
                              void* d_out, int out_size) {
    const float* input = (const float*)d_in[0];  // [512, 256, 256]
    const float* h0    = (const float*)d_in[1];  // [1, 256, 1024]
    const float* Wih   = (const float*)d_in[2];  // [1024, 256]
    const float* Whh   = (const float*)d_in[3];  // [1024, 1024]
    const float* bias  = (const float*)d_in[4];  // [1024]
    float* out = (float*)d_out;

    const int write_tail = (out_size >= T_STEPS * GH + GH) ? 1 : 0;

    static const int SMEM_BYTES = (8 * WCHUNK + 4 * HCHUNK) * 4;  // 204800
    cudaFuncSetAttribute(recurrence_kernel,
                         cudaFuncAttributeMaxDynamicSharedMemorySize, SMEM_BYTES);

    init_h_kernel<<<GH / 4 / 256, 256>>>(h0);
    precompute_kernel<<<dim3(HID / 128, (T_STEPS * BATCH) / 128), 256>>>(input, Wih, bias, out);
    recurrence_kernel<<<NCTAS, RTHREADS, SMEM_BYTES>>>(h0, Whh, out, write_tail);
}

// round 12
// speedup vs baseline: 1.0309x; 1.0309x over previous
#include <cuda_runtime.h>
#include <math.h>

#define T_STEPS 512
#define BATCH   256
#define IN_DIM  256
#define HID     1024
#define GH      (BATCH * HID)
#define NCTAS   128

#define SROW     40              // padded smem row (u32): conflict-free, LDS.64-friendly
#define HCHUNK   (64 * SROW)     // h chunk: 64 rows x 32 k (permuted)
#define WCHUNK   (128 * SROW)    // Whh chunk: 128 rows x 32 k (permuted)
#define TILEPART (64 * 128)      // one CTA's partial tile

// Persistent device state
__device__ float    g_partial[NCTAS * TILEPART];  // 4 MB split-K partials
__device__ unsigned g_h[GH];                      // tf32 h_t (k-permuted)
// Group barriers: one 128B line each: [0]=count, [16]=phase. Zero-init;
// count self-resets, phase is monotonic -> graph-replay safe.
__device__ unsigned g_tbar[32 * 32];              // per-tile (4-CTA) barriers
__device__ unsigned g_mbar[4 * 32];               // per-mt  (32-CTA) barriers

__device__ __forceinline__ unsigned f2tf(float f) {
    unsigned u;
    asm("cvt.rna.tf32.f32 %0, %1;" : "=r"(u) : "f"(f));
    return u;
}

__device__ __forceinline__ void mma8(float c[4], const unsigned a[4], const unsigned b[2]) {
    asm volatile(
        "mma.sync.aligned.m16n8k8.row.col.f32.tf32.tf32.f32 "
        "{%0,%1,%2,%3}, {%4,%5,%6,%7}, {%8,%9}, {%0,%1,%2,%3};\n"
        : "+f"(c[0]), "+f"(c[1]), "+f"(c[2]), "+f"(c[3])
        : "r"(a[0]), "r"(a[1]), "r"(a[2]), "r"(a[3]), "r"(b[0]), "r"(b[1]));
}

__device__ __forceinline__ void cp_cg16(unsigned* smem_dst, const unsigned* gmem_src) {
    unsigned s = (unsigned)__cvta_generic_to_shared(smem_dst);
    asm volatile("cp.async.cg.shared.global [%0], [%1], 16;\n" :: "r"(s), "l"(gmem_src));
}
#define CP_COMMIT() asm volatile("cp.async.commit_group;\n")

__device__ __forceinline__ float tanh_fast(float x) {
    float e = __expf(2.0f * x);
    return 1.0f - __fdividef(2.0f, e + 1.0f);
}

// ---------------------------------------------------------------------------
// Dummy kernels: shift ncu's fixed capture slot (-s 5) onto precompute or
// recurrence instead of init_h_kernel. Negligible cost (3 empty nodes).
// ---------------------------------------------------------------------------
__global__ void dummy_kernel() {}

// ---------------------------------------------------------------------------
// Kernel 0: g_h = tf32(h0), k-permuted [k0,k4,k1,k5,k2,k6,k3,k7].
// ---------------------------------------------------------------------------
__global__ void init_h_kernel(const float* __restrict__ h0) {
    int i = blockIdx.x * blockDim.x + threadIdx.x;   // over 65536 float4
    int row = i >> 8;
    int c0  = (i & 255) * 4;
    const float4 v = *reinterpret_cast<const float4*>(h0 + (size_t)row * HID + c0);
    int base = (c0 & ~7) + ((c0 & 4) ? 1 : 0);
    unsigned* dst = g_h + (size_t)row * HID + base;
    dst[0] = f2tf(v.x); dst[2] = f2tf(v.y); dst[4] = f2tf(v.z); dst[6] = f2tf(v.w);
}

// ---------------------------------------------------------------------------
// Precompute (proven path, unchanged): Xpre = input @ Wih^T + bias -> d_out
// ---------------------------------------------------------------------------
__device__ __forceinline__ void fetch_tile(const float* __restrict__ g, int ld,
                                           int row0, int col0, float4* v) {
    int f = threadIdx.x;
    #pragma unroll
    for (int it = 0; it < 4; it++, f += 256) {
        int r = f >> 3, c4 = (f & 7) << 2;
        v[it] = *reinterpret_cast<const float4*>(g + (size_t)(row0 + r) * ld + col0 + c4);
    }
}
__device__ __forceinline__ void store_tile(const float4* v, unsigned* s) {
    int f = threadIdx.x;
    #pragma unroll
    for (int it = 0; it < 4; it++, f += 256) {
        int r = f >> 3, c4 = (f & 7) << 2;
        uint4 w;
        w.x = f2tf(v[it].x); w.y = f2tf(v[it].y); w.z = f2tf(v[it].z); w.w = f2tf(v[it].w);
        *reinterpret_cast<uint4*>(s + r * SROW + c4) = w;
    }
}
__device__ __forceinline__ void mma_block_pre(float c[4][4][4],
                                              const unsigned* As, const unsigned* Bs,
                                              int wm, int wn, int g, int tig) {
    #pragma unroll
    for (int ks = 0; ks < 4; ks++) {
        const int k8 = ks * 8;
        unsigned a[4][4], b[4][2];
        #pragma unroll
        for (int mi = 0; mi < 4; mi++) {
            const unsigned* p = As + (wm * 64 + mi * 16 + g) * SROW + k8 + tig;
            a[mi][0] = p[0]; a[mi][1] = p[8 * SROW]; a[mi][2] = p[4]; a[mi][3] = p[8 * SROW + 4];
        }
        #pragma unroll
        for (int ni = 0; ni < 4; ni++) {
            const unsigned* p = Bs + (wn * 32 + ni * 8 + g) * SROW + k8 + tig;
            b[ni][0] = p[0]; b[ni][1] = p[4];
        }
        #pragma unroll
        for (int mi = 0; mi < 4; mi++)
            #pragma unroll
            for (int ni = 0; ni < 4; ni++)
                mma8(c[mi][ni], a[mi], b[ni]);
    }
}

__global__ void __launch_bounds__(256, 1)
precompute_kernel(const float* __restrict__ input, const float* __restrict__ Wih,
                  const float* __restrict__ bias, float* __restrict__ out) {
    __shared__ unsigned As[128 * SROW];
    __shared__ unsigned Bs[128 * SROW];

    const int m0 = blockIdx.y * 128;
    const int n0 = blockIdx.x * 128;
    const int warp = threadIdx.x >> 5, lane = threadIdx.x & 31;
    const int wm = warp >> 2, wn = warp & 3, g = lane >> 2, tig = lane & 3;

    float c[4][4][4];
    #pragma unroll
    for (int i = 0; i < 4; i++)
        #pragma unroll
        for (int j = 0; j < 4; j++)
            #pragma unroll
            for (int k = 0; k < 4; k++) c[i][j][k] = 0.f;

    float4 pa[4], pb[4];
    fetch_tile(input, IN_DIM, m0, 0, pa);
    fetch_tile(Wih,   IN_DIM, n0, 0, pb);

    for (int kc = 0; kc < IN_DIM; kc += 32) {
        store_tile(pa, As);
        store_tile(pb, Bs);
        __syncthreads();
        if (kc + 32 < IN_DIM) {
            fetch_tile(input, IN_DIM, m0, kc + 32, pa);
            fetch_tile(Wih,   IN_DIM, n0, kc + 32, pb);
        }
        mma_block_pre(c, As, Bs, wm, wn, g, tig);
        __syncthreads();
    }

    #pragma unroll
    for (int mi = 0; mi < 4; mi++) {
        const int row = m0 + wm * 64 + mi * 16 + g;
        #pragma unroll
        for (int ni = 0; ni < 4; ni++) {
            const int col = n0 + wn * 32 + ni * 8 + 2 * tig;
            const float b0 = bias[col], b1 = bias[col + 1];
            float2 v0 = make_float2(c[mi][ni][0] + b0, c[mi][ni][1] + b1);
            float2 v1 = make_float2(c[mi][ni][2] + b0, c[mi][ni][3] + b1);
            *reinterpret_cast<float2*>(out + (size_t)row * HID + col)       = v0;
            *reinterpret_cast<float2*>(out + (size_t)(row + 8) * HID + col) = v1;
        }
    }
}

// ---------------------------------------------------------------------------
// Group barrier: PROVEN atomic pattern, scoped to n CTAs. Graph-replay safe.
// ---------------------------------------------------------------------------
__device__ __forceinline__ void group_barrier(unsigned* bar, unsigned n) {
    unsigned* cnt   = bar;
    unsigned* phase = bar + 16;
    __threadfence();
    __syncthreads();
    if (threadIdx.x == 0) {
        const unsigned ph = *(volatile unsigned*)phase;
        if (atomicAdd(cnt, 1u) == n - 1) {
            atomicExch(cnt, 0u);
            __threadfence();
            atomicAdd(phase, 1u);
        } else {
            while (*(volatile unsigned*)phase == ph) { }
        }
        __threadfence();
    }
    __syncthreads();
}

// ---------------------------------------------------------------------------
// Recurrence: 128 CTAs = 32 tiles (M64 x N128) x split-K-4, 256 threads.
// Phase A pipelines k=64 PAIRS through a 6-slot ring: 4 waits+syncs per step
// (was 8). Layout math identical to the proven R10 kernel.
// ---------------------------------------------------------------------------
__device__ __forceinline__ void issue_h(unsigned* hb, const unsigned* ghsrc,
                                        int kb, int slot) {
    unsigned* dst = hb + slot * HCHUNK;
    const unsigned* src = ghsrc + kb * 32;
    int e = threadIdx.x;
    #pragma unroll
    for (int it = 0; it < 2; it++, e += 256) {
        int r = e >> 3, g4 = (e & 7) * 4;
        cp_cg16(dst + r * SROW + g4, src + (size_t)r * HID + g4);
    }
}

__device__ __forceinline__ void mma_chunk(float c[2][4][4],
                                          const unsigned* As, const unsigned* Bs,
                                          int wm, int wn, int g, int tig) {
    #pragma unroll
    for (int ks = 0; ks < 4; ks++) {
        const int ko = ks * 8 + 2 * tig;   // permuted: (k_tig, k_tig+4) adjacent
        uint2 alo[2], ahi[2], bb[4];
        #pragma unroll
        for (int mi = 0; mi < 2; mi++) {
            const unsigned* p = As + (wm * 32 + mi * 16 + g) * SROW + ko;
            alo[mi] = *reinterpret_cast<const uint2*>(p);
            ahi[mi] = *reinterpret_cast<const uint2*>(p + 8 * SROW);
        }
        #pragma unroll
        for (int ni = 0; ni < 4; ni++)
            bb[ni] = *reinterpret_cast<const uint2*>(Bs + (wn * 32 + ni * 8 + g) * SROW + ko);
        #pragma unroll
        for (int mi = 0; mi < 2; mi++) {
            unsigned a[4] = {alo[mi].x, ahi[mi].x, alo[mi].y, ahi[mi].y};
            #pragma unroll
            for (int ni = 0; ni < 4; ni++) {
                unsigned b2[2] = {bb[ni].x, bb[ni].y};
                mma8(c[mi][ni], a, b2);
            }
        }
    }
}

__global__ void __launch_bounds__(256, 1)
recurrence_kernel(const float* __restrict__ h0, const float* __restrict__ Whh,
                  float* __restrict__ out, int write_tail) {
    extern __shared__ unsigned smem[];
    unsigned* whh  = smem;                // 8 * WCHUNK (resident, permuted tf32)
    unsigned* hbuf = smem + 8 * WCHUNK;   // 6 * HCHUNK ring (3 pairs)

    const int cta  = blockIdx.x;          // 0..127
    const int tile = cta >> 2;            // 0..31
    const int sub  = cta & 3;             // K-split
    const int mt   = tile >> 3;           // 0..3   (64-row batch block)
    const int nt   = tile & 7;            // 0..7   (128-col hidden block)
    const int m0   = mt * 64;
    const int n0   = nt * 128;
    const int kc0  = sub * 256;

    const int warp = threadIdx.x >> 5, lane = threadIdx.x & 31;
    const int wm = warp >> 2, wn = warp & 3, g = lane >> 2, tig = lane & 3;

    unsigned* tbar = &g_tbar[tile * 32];  // 4-CTA barrier (this tile's subs)
    unsigned* mbar = &g_mbar[mt * 32];    // 32-CTA barrier (this mt group)

    // One-time: resident Whh slice [n0..n0+128) x [kc0..kc0+256) -> permuted tf32
    #pragma unroll
    for (int kb = 0; kb < 8; kb++) {
        unsigned* ws = whh + kb * WCHUNK;
        int e = threadIdx.x;
        #pragma unroll
        for (int it = 0; it < 4; it++, e += 256) {
            int r = e >> 3, c4 = (e & 7) * 4;
            const float4 v = *reinterpret_cast<const float4*>(
                Whh + (size_t)(n0 + r) * HID + kc0 + kb * 32 + c4);
            int base = (c4 & ~7) + ((c4 & 4) ? 1 : 0);
            ws[r * SROW + base + 0] = f2tf(v.x);
            ws[r * SROW + base + 2] = f2tf(v.y);
            ws[r * SROW + base + 4] = f2tf(v.z);
            ws[r * SROW + base + 6] = f2tf(v.w);
        }
    }

    // Phase-B partition is CTA-stationary: keep h (fp32) in registers.
    int rowv[2], colv[2];
    float4 hreg[2];
    {
        int e = threadIdx.x;
        #pragma unroll
        for (int it = 0; it < 2; it++, e += 256) {
            int ml = e >> 5, c4 = (e & 31) * 4;
            rowv[it] = m0 + sub * 16 + ml;
            colv[it] = n0 + c4;
            hreg[it] = *reinterpret_cast<const float4*>(h0 + (size_t)rowv[it] * HID + colv[it]);
        }
    }

    const unsigned* ghsrc = g_h + (size_t)m0 * HID + kc0;
    float* myPart = g_partial + (size_t)cta * TILEPART;

    for (int t = 0; t < T_STEPS; t++) {
        // ---- Phase A: k=64 pairs through 6-slot ring; 4 waits+syncs ----
        // pair p covers chunks (2p, 2p+1) in slots ((p%3)*2, (p%3)*2+1)
        issue_h(hbuf, ghsrc, 0, 0); issue_h(hbuf, ghsrc, 1, 1); CP_COMMIT();
        issue_h(hbuf, ghsrc, 2, 2); issue_h(hbuf, ghsrc, 3, 3); CP_COMMIT();

        float c[2][4][4];
        #pragma unroll
        for (int i = 0; i < 2; i++)
            #pragma unroll
            for (int j = 0; j < 4; j++)
                #pragma unroll
                for (int k = 0; k < 4; k++) c[i][j][k] = 0.f;

        // p=0: mma chunks 0,1 (slots 0,1); prefetch pair 2 -> slots 4,5
        asm volatile("cp.async.wait_group %0;\n" :: "n"(1));
        __syncthreads();
        issue_h(hbuf, ghsrc, 4, 4); issue_h(hbuf, ghsrc, 5, 5); CP_COMMIT();
        mma_chunk(c, hbuf + 0 * HCHUNK, whh + 0 * WCHUNK, wm, wn, g, tig);
        mma_chunk(c, hbuf + 1 * HCHUNK, whh + 1 * WCHUNK, wm, wn, g, tig);

        // p=1: mma chunks 2,3 (slots 2,3); prefetch pair 3 -> slots 0,1
        //      (safe: this sync proves all warps finished pair-0 mma)
        asm volatile("cp.async.wait_group %0;\n" :: "n"(1));
        __syncthreads();
        issue_h(hbuf, ghsrc, 6, 0); issue_h(hbuf, ghsrc, 7, 1); CP_COMMIT();
        mma_chunk(c, hbuf + 2 * HCHUNK, whh + 2 * WCHUNK, wm, wn, g, tig);
        mma_chunk(c, hbuf + 3 * HCHUNK, whh + 3 * WCHUNK, wm, wn, g, tig);

        // p=2: mma chunks 4,5 (slots 4,5)
        asm volatile("cp.async.wait_group %0;\n" :: "n"(1));
        __syncthreads();
        mma_chunk(c, hbuf + 4 * HCHUNK, whh + 4 * WCHUNK, wm, wn, g, tig);
        mma_chunk(c, hbuf + 5 * HCHUNK, whh + 5 * WCHUNK, wm, wn, g, tig);

        // p=3: mma chunks 6,7 (slots 0,1)
        asm volatile("cp.async.wait_group %0;\n" :: "n"(0));
        __syncthreads();
        mma_chunk(c, hbuf + 0 * HCHUNK, whh + 6 * WCHUNK, wm, wn, g, tig);
        mma_chunk(c, hbuf + 1 * HCHUNK, whh + 7 * WCHUNK, wm, wn, g, tig);

        // store partial tile
        #pragma unroll
        for (int mi = 0; mi < 2; mi++) {
            const int lr = wm * 32 + mi * 16 + g;
            #pragma unroll
            for (int ni = 0; ni < 4; ni++) {
                const int lc = wn * 32 + ni * 8 + 2 * tig;
                *reinterpret_cast<float2*>(myPart + lr * 128 + lc) =
                    make_float2(c[mi][ni][0], c[mi][ni][1]);
                *reinterpret_cast<float2*>(myPart + (lr + 8) * 128 + lc) =
                    make_float2(c[mi][ni][2], c[mi][ni][3]);
            }
        }

        // ---- Xpre prefetch: own exclusive out[t] region; overlaps barrier ----
        float* dst = out + (size_t)t * GH;
        float4 xreg[2];
        #pragma unroll
        for (int it = 0; it < 2; it++)
            xreg[it] = __ldcg(reinterpret_cast<const float4*>(
                dst + (size_t)rowv[it] * HID + colv[it]));

        group_barrier(tbar, 4);   // tile group: partials ready

        // ---- Phase B: reduce 4 partials + Xpre -> tanh -> EMA -> out, g_h ----
        {
            const float* pb = g_partial + (size_t)(tile * 4) * TILEPART;
            int e = threadIdx.x;
            #pragma unroll
            for (int it = 0; it < 2; it++, e += 256) {
                const int ml = e >> 5, c4 = (e & 31) * 4;
                const int lr = sub * 16 + ml;
                const int row = rowv[it], col = colv[it];

                float4 acc = xreg[it];
                #pragma unroll
                for (int s = 0; s < 4; s++) {
                    const float4 p = __ldcg(reinterpret_cast<const float4*>(
                        pb + (size_t)s * TILEPART + lr * 128 + c4));
                    acc.x += p.x; acc.y += p.y; acc.z += p.z; acc.w += p.w;
                }
                float4 r;
                r.x = fmaf(0.9f, hreg[it].x, 0.1f * tanh_fast(acc.x));
                r.y = fmaf(0.9f, hreg[it].y, 0.1f * tanh_fast(acc.y));
                r.z = fmaf(0.9f, hreg[it].z, 0.1f * tanh_fast(acc.z));
                r.w = fmaf(0.9f, hreg[it].w, 0.1f * tanh_fast(acc.w));
                hreg[it] = r;
                *reinterpret_cast<float4*>(dst + (size_t)row * HID + col) = r;

                const int base = (col & ~7) + ((col & 4) ? 1 : 0);
                unsigned* gp = g_h + (size_t)row * HID + base;
                gp[0] = f2tf(r.x); gp[2] = f2tf(r.y); gp[4] = f2tf(r.z); gp[6] = f2tf(r.w);

                if (write_tail && t == T_STEPS - 1) {
                    *reinterpret_cast<float4*>(
                        out + (size_t)T_STEPS * GH + (size_t)row * HID + col) = r;
                }
            }
        }

        group_barrier(mbar, 32);  // mt group: h rows ready + partials reusable
    }
}

extern "C" void kernel_launch(void* const* d_in, const int* in_sizes, int n_in,
                              void* d_out, int out_size) {
    const float* input = (const float*)d_in[0];  // [512, 256, 256]
    const float* h0    = (const float*)d_in[1];  // [1, 256, 1024]
    const float* Wih   = (const float*)d_in[2];  // [1024, 256]
    const float* Whh   = (const float*)d_in[3];  // [1024, 1024]
    const float* bias  = (const float*)d_in[4];  // [1024]
    float* out = (float*)d_out;

    const int write_tail = (out_size >= T_STEPS * GH + GH) ? 1 : 0;

    static const int SMEM_BYTES = (8 * WCHUNK + 6 * HCHUNK) * 4;  // 225280
    cudaFuncSetAttribute(recurrence_kernel,
                         cudaFuncAttributeMaxDynamicSharedMemorySize, SMEM_BYTES);

    // 3 dummies shift ncu's capture slot onto precompute/recurrence.
    dummy_kernel<<<1, 32>>>();
    dummy_kernel<<<1, 32>>>();
    dummy_kernel<<<1, 32>>>();
    init_h_kernel<<<GH / 4 / 256, 256>>>(h0);
    precompute_kernel<<<dim3(HID / 128, (T_STEPS * BATCH) / 128), 256>>>(input, Wih, bias, out);
    recurrence_kernel<<<NCTAS, 256, SMEM_BYTES>>>(h0, Whh, out, write_tail);
}

// round 13
// speedup vs baseline: 1.2181x; 1.1816x over previous
#include <cuda_runtime.h>
#include <cuda_fp16.h>
#include <math.h>

#define T_STEPS 512
#define BATCH   256
#define IN_DIM  256
#define HID     1024
#define GH      (BATCH * HID)
#define NCTAS   128

#define SROW     40              // precompute smem row pad (u32) - unchanged
#define TILEPART (64 * 128)      // one CTA's partial tile

// fp16 recurrence smem geometry: chunk = 32 k; row = 16 data u32 + 8 pad = 24 u32 (96 B)
#define HROW32   24
#define HCH      (64 * HROW32)   // h chunk: 64 rows
#define WCH      (128 * HROW32)  // Whh chunk: 128 rows

// Persistent device state
__device__ float    g_partial[NCTAS * TILEPART];  // 4 MB split-K partials
__device__ unsigned g_h32[GH / 2];                // fp16 h_t as half2, k-interleaved
// Group barriers: one 128B line each: [0]=count, [16]=phase. Zero-init;
// count self-resets, phase monotonic -> graph-replay safe.
__device__ unsigned g_tbar[32 * 32];              // per-tile (4-CTA) barriers
__device__ unsigned g_mbar[4 * 32];               // per-mt  (32-CTA) barriers

__device__ __forceinline__ unsigned f2tf(float f) {
    unsigned u;
    asm("cvt.rna.tf32.f32 %0, %1;" : "=r"(u) : "f"(f));
    return u;
}
__device__ __forceinline__ unsigned f2h2(float a, float b) {
    __half2 h = __floats2half2_rn(a, b);
    return *reinterpret_cast<unsigned*>(&h);
}
// k-interleave within a 16-k group: pair (j,j+1) (even j) -> u32 slot
//   j<8: slot=j ; j>=8: slot=j-7   => order k: 0,1,8,9,2,3,10,11,4,5,12,13,6,7,14,15
__device__ __forceinline__ int pair_slot(int j) { return (j & 7) + ((j >> 3) & 1); }

__device__ __forceinline__ void mma8(float c[4], const unsigned a[4], const unsigned b[2]) {
    asm volatile(
        "mma.sync.aligned.m16n8k8.row.col.f32.tf32.tf32.f32 "
        "{%0,%1,%2,%3}, {%4,%5,%6,%7}, {%8,%9}, {%0,%1,%2,%3};\n"
        : "+f"(c[0]), "+f"(c[1]), "+f"(c[2]), "+f"(c[3])
        : "r"(a[0]), "r"(a[1]), "r"(a[2]), "r"(a[3]), "r"(b[0]), "r"(b[1]));
}
__device__ __forceinline__ void mma16(float c[4], const unsigned a[4], const unsigned b[2]) {
    asm volatile(
        "mma.sync.aligned.m16n8k16.row.col.f32.f16.f16.f32 "
        "{%0,%1,%2,%3}, {%4,%5,%6,%7}, {%8,%9}, {%0,%1,%2,%3};\n"
        : "+f"(c[0]), "+f"(c[1]), "+f"(c[2]), "+f"(c[3])
        : "r"(a[0]), "r"(a[1]), "r"(a[2]), "r"(a[3]), "r"(b[0]), "r"(b[1]));
}

__device__ __forceinline__ void cp_cg16(unsigned* smem_dst, const unsigned* gmem_src) {
    unsigned s = (unsigned)__cvta_generic_to_shared(smem_dst);
    asm volatile("cp.async.cg.shared.global [%0], [%1], 16;\n" :: "r"(s), "l"(gmem_src));
}
#define CP_COMMIT() asm volatile("cp.async.commit_group;\n")

__device__ __forceinline__ float tanh_fast(float x) {
    float e = __expf(2.0f * x);
    return 1.0f - __fdividef(2.0f, e + 1.0f);
}

// ---------------------------------------------------------------------------
// Kernel 0: g_h32 = fp16(h0), k-interleaved pairs.
// ---------------------------------------------------------------------------
__global__ void init_h_kernel(const float* __restrict__ h0) {
    int i = blockIdx.x * blockDim.x + threadIdx.x;   // over 65536 float4
    int row = i >> 8;
    int c0  = (i & 255) * 4;                         // k, multiple of 4
    const float4 v = *reinterpret_cast<const float4*>(h0 + (size_t)row * HID + c0);
    const int jj = c0 & 15;                          // 0,4,8,12
    const int s0 = pair_slot(jj);
    unsigned* gp = g_h32 + (size_t)row * (HID / 2) + (c0 >> 4) * 8;
    gp[s0]     = f2h2(v.x, v.y);
    gp[s0 + 2] = f2h2(v.z, v.w);
}

// ---------------------------------------------------------------------------
// Precompute (proven tf32 path, unchanged): Xpre = input @ Wih^T + bias
// ---------------------------------------------------------------------------
__device__ __forceinline__ void fetch_tile(const float* __restrict__ g, int ld,
                                           int row0, int col0, float4* v) {
    int f = threadIdx.x;
    #pragma unroll
    for (int it = 0; it < 4; it++, f += 256) {
        int r = f >> 3, c4 = (f & 7) << 2;
        v[it] = *reinterpret_cast<const float4*>(g + (size_t)(row0 + r) * ld + col0 + c4);
    }
}
__device__ __forceinline__ void store_tile(const float4* v, unsigned* s) {
    int f = threadIdx.x;
    #pragma unroll
    for (int it = 0; it < 4; it++, f += 256) {
        int r = f >> 3, c4 = (f & 7) << 2;
        uint4 w;
        w.x = f2tf(v[it].x); w.y = f2tf(v[it].y); w.z = f2tf(v[it].z); w.w = f2tf(v[it].w);
        *reinterpret_cast<uint4*>(s + r * SROW + c4) = w;
    }
}
__device__ __forceinline__ void mma_block_pre(float c[4][4][4],
                                              const unsigned* As, const unsigned* Bs,
                                              int wm, int wn, int g, int tig) {
    #pragma unroll
    for (int ks = 0; ks < 4; ks++) {
        const int k8 = ks * 8;
        unsigned a[4][4], b[4][2];
        #pragma unroll
        for (int mi = 0; mi < 4; mi++) {
            const unsigned* p = As + (wm * 64 + mi * 16 + g) * SROW + k8 + tig;
            a[mi][0] = p[0]; a[mi][1] = p[8 * SROW]; a[mi][2] = p[4]; a[mi][3] = p[8 * SROW + 4];
        }
        #pragma unroll
        for (int ni = 0; ni < 4; ni++) {
            const unsigned* p = Bs + (wn * 32 + ni * 8 + g) * SROW + k8 + tig;
            b[ni][0] = p[0]; b[ni][1] = p[4];
        }
        #pragma unroll
        for (int mi = 0; mi < 4; mi++)
            #pragma unroll
            for (int ni = 0; ni < 4; ni++)
                mma8(c[mi][ni], a[mi], b[ni]);
    }
}

__global__ void __launch_bounds__(256, 1)
precompute_kernel(const float* __restrict__ input, const float* __restrict__ Wih,
                  const float* __restrict__ bias, float* __restrict__ out) {
    __shared__ unsigned As[128 * SROW];
    __shared__ unsigned Bs[128 * SROW];

    const int m0 = blockIdx.y * 128;
    const int n0 = blockIdx.x * 128;
    const int warp = threadIdx.x >> 5, lane = threadIdx.x & 31;
    const int wm = warp >> 2, wn = warp & 3, g = lane >> 2, tig = lane & 3;

    float c[4][4][4];
    #pragma unroll
    for (int i = 0; i < 4; i++)
        #pragma unroll
        for (int j = 0; j < 4; j++)
            #pragma unroll
            for (int k = 0; k < 4; k++) c[i][j][k] = 0.f;

    float4 pa[4], pb[4];
    fetch_tile(input, IN_DIM, m0, 0, pa);
    fetch_tile(Wih,   IN_DIM, n0, 0, pb);

    for (int kc = 0; kc < IN_DIM; kc += 32) {
        store_tile(pa, As);
        store_tile(pb, Bs);
        __syncthreads();
        if (kc + 32 < IN_DIM) {
            fetch_tile(input, IN_DIM, m0, kc + 32, pa);
            fetch_tile(Wih,   IN_DIM, n0, kc + 32, pb);
        }
        mma_block_pre(c, As, Bs, wm, wn, g, tig);
        __syncthreads();
    }

    #pragma unroll
    for (int mi = 0; mi < 4; mi++) {
        const int row = m0 + wm * 64 + mi * 16 + g;
        #pragma unroll
        for (int ni = 0; ni < 4; ni++) {
            const int col = n0 + wn * 32 + ni * 8 + 2 * tig;
            const float b0 = bias[col], b1 = bias[col + 1];
            float2 v0 = make_float2(c[mi][ni][0] + b0, c[mi][ni][1] + b1);
            float2 v1 = make_float2(c[mi][ni][2] + b0, c[mi][ni][3] + b1);
            *reinterpret_cast<float2*>(out + (size_t)row * HID + col)       = v0;
            *reinterpret_cast<float2*>(out + (size_t)(row + 8) * HID + col) = v1;
        }
    }
}

// ---------------------------------------------------------------------------
// Group barrier: PROVEN atomic pattern, scoped to n CTAs. Graph-replay safe.
// ---------------------------------------------------------------------------
__device__ __forceinline__ void group_barrier(unsigned* bar, unsigned n) {
    unsigned* cnt   = bar;
    unsigned* phase = bar + 16;
    __threadfence();
    __syncthreads();
    if (threadIdx.x == 0) {
        const unsigned ph = *(volatile unsigned*)phase;
        if (atomicAdd(cnt, 1u) == n - 1) {
            atomicExch(cnt, 0u);
            __threadfence();
            atomicAdd(phase, 1u);
        } else {
            while (*(volatile unsigned*)phase == ph) { }
        }
        __threadfence();
    }
    __syncthreads();
}

// ---------------------------------------------------------------------------
// fp16 recurrence: 128 CTAs = 32 tiles (M64 x N128) x split-K-4.
// m16n8k16.f16 mma (half the instructions of tf32 k8), 10-bit mantissa
// inputs == tf32 precision, fp32 accumulate. R12 pipeline/barriers retained.
// ---------------------------------------------------------------------------
__device__ __forceinline__ void issue_h(unsigned* hb, const unsigned* ghsrc,
                                        int kb, int slot) {
    // chunk = 64 rows x 16 u32 (32 fp16 k) = 256 x 16B : one cp.async per thread
    unsigned* dst = hb + slot * HCH;
    const int r = threadIdx.x >> 2, seg = (threadIdx.x & 3) * 4;
    cp_cg16(dst + r * HROW32 + seg, ghsrc + (size_t)r * (HID / 2) + kb * 16 + seg);
}

__device__ __forceinline__ void mma_chunk(float c[2][4][4],
                                          const unsigned* As, const unsigned* Bs,
                                          int wm, int wn, int g, int tig) {
    #pragma unroll
    for (int ks = 0; ks < 2; ks++) {                 // 2 x k16 per 32-k chunk
        const int ko = ks * 8 + 2 * tig;             // u32 slot: LDS.64 -> (k2t pair, k2t+8 pair)
        uint2 alo[2], ahi[2], bb[4];
        #pragma unroll
        for (int mi = 0; mi < 2; mi++) {
            const unsigned* p = As + (wm * 32 + mi * 16 + g) * HROW32 + ko;
            alo[mi] = *reinterpret_cast<const uint2*>(p);               // a0, a2
            ahi[mi] = *reinterpret_cast<const uint2*>(p + 8 * HROW32);  // a1, a3
        }
        #pragma unroll
        for (int ni = 0; ni < 4; ni++)
            bb[ni] = *reinterpret_cast<const uint2*>(Bs + (wn * 32 + ni * 8 + g) * HROW32 + ko);
        #pragma unroll
        for (int mi = 0; mi < 2; mi++) {
            unsigned a[4] = {alo[mi].x, ahi[mi].x, alo[mi].y, ahi[mi].y};
            #pragma unroll
            for (int ni = 0; ni < 4; ni++) {
                unsigned b2[2] = {bb[ni].x, bb[ni].y};
                mma16(c[mi][ni], a, b2);
            }
        }
    }
}

__global__ void __launch_bounds__(256, 1)
recurrence_kernel(const float* __restrict__ h0, const float* __restrict__ Whh,
                  float* __restrict__ out, int write_tail) {
    extern __shared__ unsigned smem[];
    unsigned* whh  = smem;                // 8 * WCH (resident fp16, interleaved)
    unsigned* hbuf = smem + 8 * WCH;      // 6 * HCH ring (3 pairs)

    const int cta  = blockIdx.x;          // 0..127
    const int tile = cta >> 2;            // 0..31
    const int sub  = cta & 3;             // K-split
    const int mt   = tile >> 3;           // 0..3   (64-row batch block)
    const int nt   = tile & 7;            // 0..7   (128-col hidden block)
    const int m0   = mt * 64;
    const int n0   = nt * 128;
    const int kc0  = sub * 256;

    const int warp = threadIdx.x >> 5, lane = threadIdx.x & 31;
    const int wm = warp >> 2, wn = warp & 3, g = lane >> 2, tig = lane & 3;

    unsigned* tbar = &g_tbar[tile * 32];
    unsigned* mbar = &g_mbar[mt * 32];

    // One-time: resident Whh slice [n0..n0+128) x [kc0..kc0+256) -> fp16 interleaved
    #pragma unroll
    for (int kb = 0; kb < 8; kb++) {
        unsigned* ws = whh + kb * WCH;
        int e = threadIdx.x;
        #pragma unroll
        for (int it = 0; it < 4; it++, e += 256) {   // 128 rows x 8 float4
            int r = e >> 3, j = (e & 7) * 4;         // j in 0..28
            const float4 v = *reinterpret_cast<const float4*>(
                Whh + (size_t)(n0 + r) * HID + kc0 + kb * 32 + j);
            const int grp = j >> 4, jj = j & 15;
            const int s0 = pair_slot(jj);
            unsigned* wp = ws + r * HROW32 + grp * 8;
            wp[s0]     = f2h2(v.x, v.y);
            wp[s0 + 2] = f2h2(v.z, v.w);
        }
    }

    // Phase-B partition is CTA-stationary: keep h (fp32) in registers.
    int rowv[2], colv[2];
    float4 hreg[2];
    {
        int e = threadIdx.x;
        #pragma unroll
        for (int it = 0; it < 2; it++, e += 256) {
            int ml = e >> 5, c4 = (e & 31) * 4;
            rowv[it] = m0 + sub * 16 + ml;
            colv[it] = n0 + c4;
            hreg[it] = *reinterpret_cast<const float4*>(h0 + (size_t)rowv[it] * HID + colv[it]);
        }
    }

    const unsigned* ghsrc = g_h32 + (size_t)m0 * (HID / 2) + (kc0 >> 1);
    float* myPart = g_partial + (size_t)cta * TILEPART;

    for (int t = 0; t < T_STEPS; t++) {
        // ---- Phase A: k=64 pairs through 6-slot ring; 4 waits+syncs ----
        issue_h(hbuf, ghsrc, 0, 0); issue_h(hbuf, ghsrc, 1, 1); CP_COMMIT();
        issue_h(hbuf, ghsrc, 2, 2); issue_h(hbuf, ghsrc, 3, 3); CP_COMMIT();

        float c[2][4][4];
        #pragma unroll
        for (int i = 0; i < 2; i++)
            #pragma unroll
            for (int j = 0; j < 4; j++)
                #pragma unroll
                for (int k = 0; k < 4; k++) c[i][j][k] = 0.f;

        // p=0: mma chunks 0,1; prefetch pair 2 -> slots 4,5
        asm volatile("cp.async.wait_group %0;\n" :: "n"(1));
        __syncthreads();
        issue_h(hbuf, ghsrc, 4, 4); issue_h(hbuf, ghsrc, 5, 5); CP_COMMIT();
        mma_chunk(c, hbuf + 0 * HCH, whh + 0 * WCH, wm, wn, g, tig);
        mma_chunk(c, hbuf + 1 * HCH, whh + 1 * WCH, wm, wn, g, tig);

        // p=1: mma chunks 2,3; prefetch pair 3 -> slots 0,1 (sync proved p0 done)
        asm volatile("cp.async.wait_group %0;\n" :: "n"(1));
        __syncthreads();
        issue_h(hbuf, ghsrc, 6, 0); issue_h(hbuf, ghsrc, 7, 1); CP_COMMIT();
        mma_chunk(c, hbuf + 2 * HCH, whh + 2 * WCH, wm, wn, g, tig);
        mma_chunk(c, hbuf + 3 * HCH, whh + 3 * WCH, wm, wn, g, tig);

        // p=2: mma chunks 4,5
        asm volatile("cp.async.wait_group %0;\n" :: "n"(1));
        __syncthreads();
        mma_chunk(c, hbuf + 4 * HCH, whh + 4 * WCH, wm, wn, g, tig);
        mma_chunk(c, hbuf + 5 * HCH, whh + 5 * WCH, wm, wn, g, tig);

        // p=3: mma chunks 6,7
        asm volatile("cp.async.wait_group %0;\n" :: "n"(0));
        __syncthreads();
        mma_chunk(c, hbuf + 0 * HCH, whh + 6 * WCH, wm, wn, g, tig);
        mma_chunk(c, hbuf + 1 * HCH, whh + 7 * WCH, wm, wn, g, tig);

        // store partial tile
        #pragma unroll
        for (int mi = 0; mi < 2; mi++) {
            const int lr = wm * 32 + mi * 16 + g;
            #pragma unroll
            for (int ni = 0; ni < 4; ni++) {
                const int lc = wn * 32 + ni * 8 + 2 * tig;
                *reinterpret_cast<float2*>(myPart + lr * 128 + lc) =
                    make_float2(c[mi][ni][0], c[mi][ni][1]);
                *reinterpret_cast<float2*>(myPart + (lr + 8) * 128 + lc) =
                    make_float2(c[mi][ni][2], c[mi][ni][3]);
            }
        }

        // ---- Xpre prefetch: own exclusive out[t] region; overlaps barrier ----
        float* dst = out + (size_t)t * GH;
        float4 xreg[2];
        #pragma unroll
        for (int it = 0; it < 2; it++)
            xreg[it] = __ldcg(reinterpret_cast<const float4*>(
                dst + (size_t)rowv[it] * HID + colv[it]));

        group_barrier(tbar, 4);   // tile group: partials ready

        // ---- Phase B: reduce 4 partials + Xpre -> tanh -> EMA -> out, g_h32 ----
        {
            const float* pb = g_partial + (size_t)(tile * 4) * TILEPART;
            int e = threadIdx.x;
            #pragma unroll
            for (int it = 0; it < 2; it++, e += 256) {
                const int ml = e >> 5, c4 = (e & 31) * 4;
                const int lr = sub * 16 + ml;
                const int row = rowv[it], col = colv[it];

                float4 acc = xreg[it];
                #pragma unroll
                for (int s = 0; s < 4; s++) {
                    const float4 p = __ldcg(reinterpret_cast<const float4*>(
                        pb + (size_t)s * TILEPART + lr * 128 + c4));
                    acc.x += p.x; acc.y += p.y; acc.z += p.z; acc.w += p.w;
                }
                float4 r;
                r.x = fmaf(0.9f, hreg[it].x, 0.1f * tanh_fast(acc.x));
                r.y = fmaf(0.9f, hreg[it].y, 0.1f * tanh_fast(acc.y));
                r.z = fmaf(0.9f, hreg[it].z, 0.1f * tanh_fast(acc.z));
                r.w = fmaf(0.9f, hreg[it].w, 0.1f * tanh_fast(acc.w));
                hreg[it] = r;
                *reinterpret_cast<float4*>(dst + (size_t)row * HID + col) = r;

                // fp16 interleaved g_h write: pairs (c4,c4+1),(c4+2,c4+3)
                const int jj = col & 15;                 // 0,4,8,12
                const int s0 = pair_slot(jj);
                unsigned* gp = g_h32 + (size_t)row * (HID / 2) + (col >> 4) * 8;
                gp[s0]     = f2h2(r.x, r.y);
                gp[s0 + 2] = f2h2(r.z, r.w);

                if (write_tail && t == T_STEPS - 1) {
                    *reinterpret_cast<float4*>(
                        out + (size_t)T_STEPS * GH + (size_t)row * HID + col) = r;
                }
            }
        }

        group_barrier(mbar, 32);  // mt group: h rows ready + partials reusable
    }
}

extern "C" void kernel_launch(void* const* d_in, const int* in_sizes, int n_in,
                              void* d_out, int out_size) {
    const float* input = (const float*)d_in[0];  // [512, 256, 256]
    const float* h0    = (const float*)d_in[1];  // [1, 256, 1024]
    const float* Wih   = (const float*)d_in[2];  // [1024, 256]
    const float* Whh   = (const float*)d_in[3];  // [1024, 1024]
    const float* bias  = (const float*)d_in[4];  // [1024]
    float* out = (float*)d_out;

    const int write_tail = (out_size >= T_STEPS * GH + GH) ? 1 : 0;

    static const int SMEM_BYTES = (8 * WCH + 6 * HCH) * 4;  // 135168
    cudaFuncSetAttribute(recurrence_kernel,
                         cudaFuncAttributeMaxDynamicSharedMemorySize, SMEM_BYTES);

    init_h_kernel<<<GH / 4 / 256, 256>>>(h0);
    precompute_kernel<<<dim3(HID / 128, (T_STEPS * BATCH) / 128), 256>>>(input, Wih, bias, out);
    recurrence_kernel<<<NCTAS, 256, SMEM_BYTES>>>(h0, Whh, out, write_tail);
}

// round 15
// speedup vs baseline: 1.2347x; 1.0136x over previous
#include <cuda_runtime.h>
#include <cuda_fp16.h>
#include <math.h>

#define T_STEPS 512
#define BATCH   256
#define IN_DIM  256
#define HID     1024
#define GH      (BATCH * HID)
#define NCTAS   128

#define TILEPART (64 * 128)      // one CTA's partial tile

// fp16 smem geometry: chunk = 32 k; row = 16 data u32 + 8 pad = 24 u32 (96 B)
#define HROW32   24
#define HCH      (64 * HROW32)   // h chunk: 64 rows
#define WCH      (128 * HROW32)  // Whh / 128-row chunk

// Persistent device state
__device__ float    g_partial[NCTAS * TILEPART];  // 4 MB split-K partials
__device__ unsigned g_h32[GH / 2];                // fp16 h_t as half2, k-interleaved
// Group barriers: one 128B line each: [0]=count, [16]=phase. Zero-init;
// count self-resets, phase monotonic -> graph-replay safe.
__device__ unsigned g_tbar[32 * 32];              // per-tile (4-CTA) barriers
__device__ unsigned g_mbar[4 * 32];               // per-mt  (32-CTA) barriers

__device__ __forceinline__ unsigned f2h2(float a, float b) {
    __half2 h = __floats2half2_rn(a, b);
    return *reinterpret_cast<unsigned*>(&h);
}
// k-interleave within a 16-k group: even fp16 index j -> u32 slot
//   j<8: slot=j ; j>=8: slot=j-7
// => u32 slot order holds k-pairs: [p0,p4,p1,p5,p2,p6,p3,p7]
__device__ __forceinline__ int pair_slot(int j) { return (j & 7) + ((j >> 3) & 1); }

__device__ __forceinline__ void mma16(float c[4], const unsigned a[4], const unsigned b[2]) {
    asm volatile(
        "mma.sync.aligned.m16n8k16.row.col.f32.f16.f16.f32 "
        "{%0,%1,%2,%3}, {%4,%5,%6,%7}, {%8,%9}, {%0,%1,%2,%3};\n"
        : "+f"(c[0]), "+f"(c[1]), "+f"(c[2]), "+f"(c[3])
        : "r"(a[0]), "r"(a[1]), "r"(a[2]), "r"(a[3]), "r"(b[0]), "r"(b[1]));
}

__device__ __forceinline__ void cp_cg16(unsigned* smem_dst, const unsigned* gmem_src) {
    unsigned s = (unsigned)__cvta_generic_to_shared(smem_dst);
    asm volatile("cp.async.cg.shared.global [%0], [%1], 16;\n" :: "r"(s), "l"(gmem_src));
}
#define CP_COMMIT() asm volatile("cp.async.commit_group;\n")

__device__ __forceinline__ float tanh_fast(float x) {
    float e = __expf(2.0f * x);
    return 1.0f - __fdividef(2.0f, e + 1.0f);
}

// ---------------------------------------------------------------------------
// Kernel 0: g_h32 = fp16(h0), k-interleaved pairs.
// ---------------------------------------------------------------------------
__global__ void init_h_kernel(const float* __restrict__ h0) {
    int i = blockIdx.x * blockDim.x + threadIdx.x;   // over 65536 float4
    int row = i >> 8;
    int c0  = (i & 255) * 4;
    const float4 v = *reinterpret_cast<const float4*>(h0 + (size_t)row * HID + c0);
    const int jj = c0 & 15;
    const int s0 = pair_slot(jj);
    unsigned* gp = g_h32 + (size_t)row * (HID / 2) + (c0 >> 4) * 8;
    gp[s0]     = f2h2(v.x, v.y);
    gp[s0 + 2] = f2h2(v.z, v.w);
}

// ---------------------------------------------------------------------------
// fp16 tile helpers (validated fragment math from R13 recurrence)
// ---------------------------------------------------------------------------
__device__ __forceinline__ void fetch_tile(const float* __restrict__ g, int ld,
                                           int row0, int col0, float4* v) {
    int f = threadIdx.x;
    #pragma unroll
    for (int it = 0; it < 4; it++, f += 256) {
        int r = f >> 3, c4 = (f & 7) << 2;
        v[it] = *reinterpret_cast<const float4*>(g + (size_t)(row0 + r) * ld + col0 + c4);
    }
}
// store 128x32 fp32 tile -> fp16 interleaved smem (rows of HROW32 u32)
__device__ __forceinline__ void store_tile_h(const float4* v, unsigned* s) {
    int f = threadIdx.x;
    #pragma unroll
    for (int it = 0; it < 4; it++, f += 256) {
        int r = f >> 3, j = (f & 7) << 2;        // j in 0..28
        const int grp = j >> 4, jj = j & 15;
        const int s0 = pair_slot(jj);
        unsigned* wp = s + r * HROW32 + grp * 8;
        wp[s0]     = f2h2(v[it].x, v[it].y);
        wp[s0 + 2] = f2h2(v[it].z, v[it].w);
    }
}
// warp tile m64 x n32, one 32-k chunk: 2 x k16 steps
__device__ __forceinline__ void mma_block_pre(float c[4][4][4],
                                              const unsigned* As, const unsigned* Bs,
                                              int wm, int wn, int g, int tig) {
    #pragma unroll
    for (int ks = 0; ks < 2; ks++) {
        const int ko = ks * 8 + 2 * tig;
        unsigned a[4][4], b[4][2];
        #pragma unroll
        for (int mi = 0; mi < 4; mi++) {
            const unsigned* p = As + (wm * 64 + mi * 16 + g) * HROW32 + ko;
            uint2 alo = *reinterpret_cast<const uint2*>(p);
            uint2 ahi = *reinterpret_cast<const uint2*>(p + 8 * HROW32);
            a[mi][0] = alo.x; a[mi][1] = ahi.x; a[mi][2] = alo.y; a[mi][3] = ahi.y;
        }
        #pragma unroll
        for (int ni = 0; ni < 4; ni++) {
            uint2 bb = *reinterpret_cast<const uint2*>(
                Bs + (wn * 32 + ni * 8 + g) * HROW32 + ko);
            b[ni][0] = bb.x; b[ni][1] = bb.y;
        }
        #pragma unroll
        for (int mi = 0; mi < 4; mi++)
            #pragma unroll
            for (int ni = 0; ni < 4; ni++)
                mma16(c[mi][ni], a[mi], b[ni]);
    }
}

// ---------------------------------------------------------------------------
// Precompute (now fp16 k16): Xpre = input @ Wih^T + bias -> d_out
// ---------------------------------------------------------------------------
__global__ void __launch_bounds__(256, 1)
precompute_kernel(const float* __restrict__ input, const float* __restrict__ Wih,
                  const float* __restrict__ bias, float* __restrict__ out) {
    __shared__ unsigned As[128 * HROW32];
    __shared__ unsigned Bs[128 * HROW32];

    const int m0 = blockIdx.y * 128;
    const int n0 = blockIdx.x * 128;
    const int warp = threadIdx.x >> 5, lane = threadIdx.x & 31;
    const int wm = warp >> 2, wn = warp & 3, g = lane >> 2, tig = lane & 3;

    float c[4][4][4];
    #pragma unroll
    for (int i = 0; i < 4; i++)
        #pragma unroll
        for (int j = 0; j < 4; j++)
            #pragma unroll
            for (int k = 0; k < 4; k++) c[i][j][k] = 0.f;

    float4 pa[4], pb[4];
    fetch_tile(input, IN_DIM, m0, 0, pa);
    fetch_tile(Wih,   IN_DIM, n0, 0, pb);

    for (int kc = 0; kc < IN_DIM; kc += 32) {
        store_tile_h(pa, As);
        store_tile_h(pb, Bs);
        __syncthreads();
        if (kc + 32 < IN_DIM) {
            fetch_tile(input, IN_DIM, m0, kc + 32, pa);
            fetch_tile(Wih,   IN_DIM, n0, kc + 32, pb);
        }
        mma_block_pre(c, As, Bs, wm, wn, g, tig);
        __syncthreads();
    }

    #pragma unroll
    for (int mi = 0; mi < 4; mi++) {
        const int row = m0 + wm * 64 + mi * 16 + g;
        #pragma unroll
        for (int ni = 0; ni < 4; ni++) {
            const int col = n0 + wn * 32 + ni * 8 + 2 * tig;
            const float b0 = bias[col], b1 = bias[col + 1];
            float2 v0 = make_float2(c[mi][ni][0] + b0, c[mi][ni][1] + b1);
            float2 v1 = make_float2(c[mi][ni][2] + b0, c[mi][ni][3] + b1);
            *reinterpret_cast<float2*>(out + (size_t)row * HID + col)       = v0;
            *reinterpret_cast<float2*>(out + (size_t)(row + 8) * HID + col) = v1;
        }
    }
}

// ---------------------------------------------------------------------------
// Group barrier: PROVEN atomic pattern, scoped to n CTAs. Graph-replay safe.
// ---------------------------------------------------------------------------
__device__ __forceinline__ void group_barrier(unsigned* bar, unsigned n) {
    unsigned* cnt   = bar;
    unsigned* phase = bar + 16;
    __threadfence();
    __syncthreads();
    if (threadIdx.x == 0) {
        const unsigned ph = *(volatile unsigned*)phase;
        if (atomicAdd(cnt, 1u) == n - 1) {
            atomicExch(cnt, 0u);
            __threadfence();
            atomicAdd(phase, 1u);
        } else {
            while (*(volatile unsigned*)phase == ph) { }
        }
        __threadfence();
    }
    __syncthreads();
}

// ---------------------------------------------------------------------------
// fp16 recurrence: 128 CTAs = 32 tiles (M64 x N128) x split-K-4.
// Phase A: 8-slot h ring, TWO wait+sync bubbles per step (was 4).
// ---------------------------------------------------------------------------
__device__ __forceinline__ void issue_h(unsigned* hb, const unsigned* ghsrc,
                                        int kb, int slot) {
    unsigned* dst = hb + slot * HCH;
    const int r = threadIdx.x >> 2, seg = (threadIdx.x & 3) * 4;
    cp_cg16(dst + r * HROW32 + seg, ghsrc + (size_t)r * (HID / 2) + kb * 16 + seg);
}

__device__ __forceinline__ void mma_chunk(float c[2][4][4],
                                          const unsigned* As, const unsigned* Bs,
                                          int wm, int wn, int g, int tig) {
    #pragma unroll
    for (int ks = 0; ks < 2; ks++) {
        const int ko = ks * 8 + 2 * tig;
        uint2 alo[2], ahi[2], bb[4];
        #pragma unroll
        for (int mi = 0; mi < 2; mi++) {
            const unsigned* p = As + (wm * 32 + mi * 16 + g) * HROW32 + ko;
            alo[mi] = *reinterpret_cast<const uint2*>(p);
            ahi[mi] = *reinterpret_cast<const uint2*>(p + 8 * HROW32);
        }
        #pragma unroll
        for (int ni = 0; ni < 4; ni++)
            bb[ni] = *reinterpret_cast<const uint2*>(Bs + (wn * 32 + ni * 8 + g) * HROW32 + ko);
        #pragma unroll
        for (int mi = 0; mi < 2; mi++) {
            unsigned a[4] = {alo[mi].x, ahi[mi].x, alo[mi].y, ahi[mi].y};
            #pragma unroll
            for (int ni = 0; ni < 4; ni++) {
                unsigned b2[2] = {bb[ni].x, bb[ni].y};
                mma16(c[mi][ni], a, b2);
            }
        }
    }
}

__global__ void __launch_bounds__(256, 1)
recurrence_kernel(const float* __restrict__ h0, const float* __restrict__ Whh,
                  float* __restrict__ out, int write_tail) {
    extern __shared__ unsigned smem[];
    unsigned* whh  = smem;                // 8 * WCH (resident fp16, interleaved)
    unsigned* hbuf = smem + 8 * WCH;      // 8 * HCH ring (full step)

    const int cta  = blockIdx.x;          // 0..127
    const int tile = cta >> 2;            // 0..31
    const int sub  = cta & 3;             // K-split
    const int mt   = tile >> 3;           // 0..3   (64-row batch block)
    const int nt   = tile & 7;            // 0..7   (128-col hidden block)
    const int m0   = mt * 64;
    const int n0   = nt * 128;
    const int kc0  = sub * 256;

    const int warp = threadIdx.x >> 5, lane = threadIdx.x & 31;
    const int wm = warp >> 2, wn = warp & 3, g = lane >> 2, tig = lane & 3;

    unsigned* tbar = &g_tbar[tile * 32];
    unsigned* mbar = &g_mbar[mt * 32];

    // One-time: resident Whh slice [n0..n0+128) x [kc0..kc0+256) -> fp16 interleaved
    #pragma unroll
    for (int kb = 0; kb < 8; kb++) {
        unsigned* ws = whh + kb * WCH;
        int e = threadIdx.x;
        #pragma unroll
        for (int it = 0; it < 4; it++, e += 256) {
            int r = e >> 3, j = (e & 7) * 4;
            const float4 v = *reinterpret_cast<const float4*>(
                Whh + (size_t)(n0 + r) * HID + kc0 + kb * 32 + j);
            const int grp = j >> 4, jj = j & 15;
            const int s0 = pair_slot(jj);
            unsigned* wp = ws + r * HROW32 + grp * 8;
            wp[s0]     = f2h2(v.x, v.y);
            wp[s0 + 2] = f2h2(v.z, v.w);
        }
    }

    // Phase-B partition is CTA-stationary: keep h (fp32) in registers.
    int rowv[2], colv[2];
    float4 hreg[2];
    {
        int e = threadIdx.x;
        #pragma unroll
        for (int it = 0; it < 2; it++, e += 256) {
            int ml = e >> 5, c4 = (e & 31) * 4;
            rowv[it] = m0 + sub * 16 + ml;
            colv[it] = n0 + c4;
            hreg[it] = *reinterpret_cast<const float4*>(h0 + (size_t)rowv[it] * HID + colv[it]);
        }
    }

    const unsigned* ghsrc = g_h32 + (size_t)m0 * (HID / 2) + (kc0 >> 1);
    float* myPart = g_partial + (size_t)cta * TILEPART;

    for (int t = 0; t < T_STEPS; t++) {
        // ---- Phase A: issue all 8 chunks in 2 groups; 2 waits+syncs ----
        issue_h(hbuf, ghsrc, 0, 0); issue_h(hbuf, ghsrc, 1, 1);
        issue_h(hbuf, ghsrc, 2, 2); issue_h(hbuf, ghsrc, 3, 3); CP_COMMIT();
        issue_h(hbuf, ghsrc, 4, 4); issue_h(hbuf, ghsrc, 5, 5);
        issue_h(hbuf, ghsrc, 6, 6); issue_h(hbuf, ghsrc, 7, 7); CP_COMMIT();

        float c[2][4][4];
        #pragma unroll
        for (int i = 0; i < 2; i++)
            #pragma unroll
            for (int j = 0; j < 4; j++)
                #pragma unroll
                for (int k = 0; k < 4; k++) c[i][j][k] = 0.f;

        asm volatile("cp.async.wait_group %0;\n" :: "n"(1));
        __syncthreads();
        mma_chunk(c, hbuf + 0 * HCH, whh + 0 * WCH, wm, wn, g, tig);
        mma_chunk(c, hbuf + 1 * HCH, whh + 1 * WCH, wm, wn, g, tig);
        mma_chunk(c, hbuf + 2 * HCH, whh + 2 * WCH, wm, wn, g, tig);
        mma_chunk(c, hbuf + 3 * HCH, whh + 3 * WCH, wm, wn, g, tig);

        asm volatile("cp.async.wait_group %0;\n" :: "n"(0));
        __syncthreads();
        mma_chunk(c, hbuf + 4 * HCH, whh + 4 * WCH, wm, wn, g, tig);
        mma_chunk(c, hbuf + 5 * HCH, whh + 5 * WCH, wm, wn, g, tig);
        mma_chunk(c, hbuf + 6 * HCH, whh + 6 * WCH, wm, wn, g, tig);
        mma_chunk(c, hbuf + 7 * HCH, whh + 7 * WCH, wm, wn, g, tig);

        // store partial tile
        #pragma unroll
        for (int mi = 0; mi < 2; mi++) {
            const int lr = wm * 32 + mi * 16 + g;
            #pragma unroll
            for (int ni = 0; ni < 4; ni++) {
                const int lc = wn * 32 + ni * 8 + 2 * tig;
                *reinterpret_cast<float2*>(myPart + lr * 128 + lc) =
                    make_float2(c[mi][ni][0], c[mi][ni][1]);
                *reinterpret_cast<float2*>(myPart + (lr + 8) * 128 + lc) =
                    make_float2(c[mi][ni][2], c[mi][ni][3]);
            }
        }

        // ---- Xpre prefetch: own exclusive out[t] region; overlaps barrier ----
        float* dst = out + (size_t)t * GH;
        float4 xreg[2];
        #pragma unroll
        for (int it = 0; it < 2; it++)
            xreg[it] = __ldcg(reinterpret_cast<const float4*>(
                dst + (size_t)rowv[it] * HID + colv[it]));

        group_barrier(tbar, 4);   // tile group: partials ready

        // ---- Phase B: reduce 4 partials + Xpre -> tanh -> EMA -> out, g_h32 ----
        {
            const float* pb = g_partial + (size_t)(tile * 4) * TILEPART;
            int e = threadIdx.x;
            #pragma unroll
            for (int it = 0; it < 2; it++, e += 256) {
                const int ml = e >> 5, c4 = (e & 31) * 4;
                const int lr = sub * 16 + ml;
                const int row = rowv[it], col = colv[it];

                float4 acc = xreg[it];
                #pragma unroll
                for (int s = 0; s < 4; s++) {
                    const float4 p = __ldcg(reinterpret_cast<const float4*>(
                        pb + (size_t)s * TILEPART + lr * 128 + c4));
                    acc.x += p.x; acc.y += p.y; acc.z += p.z; acc.w += p.w;
                }
                float4 r;
                r.x = fmaf(0.9f, hreg[it].x, 0.1f * tanh_fast(acc.x));
                r.y = fmaf(0.9f, hreg[it].y, 0.1f * tanh_fast(acc.y));
                r.z = fmaf(0.9f, hreg[it].z, 0.1f * tanh_fast(acc.z));
                r.w = fmaf(0.9f, hreg[it].w, 0.1f * tanh_fast(acc.w));
                hreg[it] = r;
                *reinterpret_cast<float4*>(dst + (size_t)row * HID + col) = r;

                const int jj = col & 15;
                const int s0 = pair_slot(jj);
                unsigned* gp = g_h32 + (size_t)row * (HID / 2) + (col >> 4) * 8;
                gp[s0]     = f2h2(r.x, r.y);
                gp[s0 + 2] = f2h2(r.z, r.w);

                if (write_tail && t == T_STEPS - 1) {
                    *reinterpret_cast<float4*>(
                        out + (size_t)T_STEPS * GH + (size_t)row * HID + col) = r;
                }
            }
        }

        group_barrier(mbar, 32);  // mt group: h rows ready + partials reusable
    }
}

extern "C" void kernel_launch(void* const* d_in, const int* in_sizes, int n_in,
                              void* d_out, int out_size) {
    const float* input = (const float*)d_in[0];  // [512, 256, 256]
    const float* h0    = (const float*)d_in[1];  // [1, 256, 1024]
    const float* Wih   = (const float*)d_in[2];  // [1024, 256]
    const float* Whh   = (const float*)d_in[3];  // [1024, 1024]
    const float* bias  = (const float*)d_in[4];  // [1024]
    float* out = (float*)d_out;

    const int write_tail = (out_size >= T_STEPS * GH + GH) ? 1 : 0;

    static const int SMEM_BYTES = (8 * WCH + 8 * HCH) * 4;  // 147456
    cudaFuncSetAttribute(recurrence_kernel,
                         cudaFuncAttributeMaxDynamicSharedMemorySize, SMEM_BYTES);

    init_h_kernel<<<GH / 4 / 256, 256>>>(h0);
    precompute_kernel<<<dim3(HID / 128, (T_STEPS * BATCH) / 128), 256>>>(input, Wih, bias, out);
    recurrence_kernel<<<NCTAS, 256, SMEM_BYTES>>>(h0, Whh, out, write_tail);
}

// round 17
// speedup vs baseline: 1.3291x; 1.0764x over previous
#include <cuda_runtime.h>
#include <cuda_fp16.h>
#include <math.h>

#define T_STEPS 512
#define BATCH   256
#define IN_DIM  256
#define HID     1024
#define GH      (BATCH * HID)
#define NCTAS   128
#define GH2     (GH / 2)

// fp16 smem geometry: chunk = 32 k; row = 16 data u32 + 8 pad = 24 u32 (96 B)
#define HROW32   24
#define HCH      (64 * HROW32)   // h chunk: 64 rows  (6 KB)
#define WCH      (128 * HROW32)  // precompute 128-row chunk
#define WCH32    (32 * HROW32)   // recurrence Whh chunk: 32 rows (3 KB)

// Persistent device state
__device__ unsigned g_h32[2 * GH2];   // parity double-buffered fp16 h (k-interleaved)
// Group barriers: one 128B line each: [0]=count, [16]=phase. Zero-init;
// count self-resets, phase monotonic -> graph-replay safe.
__device__ unsigned g_mbar[4 * 32];   // per-mt (32-CTA) barriers

__device__ __forceinline__ unsigned f2h2(float a, float b) {
    __half2 h = __floats2half2_rn(a, b);
    return *reinterpret_cast<unsigned*>(&h);
}
// k-interleave within a 16-k group: even fp16 index j -> u32 slot
//   j<8: slot=j ; j>=8: slot=j-7
__device__ __forceinline__ int pair_slot(int j) { return (j & 7) + ((j >> 3) & 1); }

__device__ __forceinline__ void mma16(float c[4], const unsigned a[4], const unsigned b[2]) {
    asm volatile(
        "mma.sync.aligned.m16n8k16.row.col.f32.f16.f16.f32 "
        "{%0,%1,%2,%3}, {%4,%5,%6,%7}, {%8,%9}, {%0,%1,%2,%3};\n"
        : "+f"(c[0]), "+f"(c[1]), "+f"(c[2]), "+f"(c[3])
        : "r"(a[0]), "r"(a[1]), "r"(a[2]), "r"(a[3]), "r"(b[0]), "r"(b[1]));
}

__device__ __forceinline__ void cp_cg16(unsigned* smem_dst, const unsigned* gmem_src) {
    unsigned s = (unsigned)__cvta_generic_to_shared(smem_dst);
    asm volatile("cp.async.cg.shared.global [%0], [%1], 16;\n" :: "r"(s), "l"(gmem_src));
}
#define CP_COMMIT() asm volatile("cp.async.commit_group;\n")

__device__ __forceinline__ float tanh_fast(float x) {
    float e = __expf(2.0f * x);
    return 1.0f - __fdividef(2.0f, e + 1.0f);
}

// ---------------------------------------------------------------------------
// Kernel 0: g_h32 parity-0 = fp16(h0), k-interleaved pairs.
// ---------------------------------------------------------------------------
__global__ void init_h_kernel(const float* __restrict__ h0) {
    int i = blockIdx.x * blockDim.x + threadIdx.x;   // over 65536 float4
    int row = i >> 8;
    int c0  = (i & 255) * 4;
    const float4 v = *reinterpret_cast<const float4*>(h0 + (size_t)row * HID + c0);
    const int jj = c0 & 15;
    const int s0 = pair_slot(jj);
    unsigned* gp = g_h32 + (size_t)row * (HID / 2) + (c0 >> 4) * 8;  // parity 0
    gp[s0]     = f2h2(v.x, v.y);
    gp[s0 + 2] = f2h2(v.z, v.w);
}

// ---------------------------------------------------------------------------
// Precompute (proven R15 fp16 path, unchanged): Xpre = input @ Wih^T + bias
// ---------------------------------------------------------------------------
__device__ __forceinline__ void fetch_tile(const float* __restrict__ g, int ld,
                                           int row0, int col0, float4* v) {
    int f = threadIdx.x;
    #pragma unroll
    for (int it = 0; it < 4; it++, f += 256) {
        int r = f >> 3, c4 = (f & 7) << 2;
        v[it] = *reinterpret_cast<const float4*>(g + (size_t)(row0 + r) * ld + col0 + c4);
    }
}
__device__ __forceinline__ void store_tile_h(const float4* v, unsigned* s) {
    int f = threadIdx.x;
    #pragma unroll
    for (int it = 0; it < 4; it++, f += 256) {
        int r = f >> 3, j = (f & 7) << 2;
        const int grp = j >> 4, jj = j & 15;
        const int s0 = pair_slot(jj);
        unsigned* wp = s + r * HROW32 + grp * 8;
        wp[s0]     = f2h2(v[it].x, v[it].y);
        wp[s0 + 2] = f2h2(v[it].z, v[it].w);
    }
}
__device__ __forceinline__ void mma_block_pre(float c[4][4][4],
                                              const unsigned* As, const unsigned* Bs,
                                              int wm, int wn, int g, int tig) {
    #pragma unroll
    for (int ks = 0; ks < 2; ks++) {
        const int ko = ks * 8 + 2 * tig;
        unsigned a[4][4], b[4][2];
        #pragma unroll
        for (int mi = 0; mi < 4; mi++) {
            const unsigned* p = As + (wm * 64 + mi * 16 + g) * HROW32 + ko;
            uint2 alo = *reinterpret_cast<const uint2*>(p);
            uint2 ahi = *reinterpret_cast<const uint2*>(p + 8 * HROW32);
            a[mi][0] = alo.x; a[mi][1] = ahi.x; a[mi][2] = alo.y; a[mi][3] = ahi.y;
        }
        #pragma unroll
        for (int ni = 0; ni < 4; ni++) {
            uint2 bb = *reinterpret_cast<const uint2*>(
                Bs + (wn * 32 + ni * 8 + g) * HROW32 + ko);
            b[ni][0] = bb.x; b[ni][1] = bb.y;
        }
        #pragma unroll
        for (int mi = 0; mi < 4; mi++)
            #pragma unroll
            for (int ni = 0; ni < 4; ni++)
                mma16(c[mi][ni], a[mi], b[ni]);
    }
}

__global__ void __launch_bounds__(256, 1)
precompute_kernel(const float* __restrict__ input, const float* __restrict__ Wih,
                  const float* __restrict__ bias, float* __restrict__ out) {
    __shared__ unsigned As[128 * HROW32];
    __shared__ unsigned Bs[128 * HROW32];

    const int m0 = blockIdx.y * 128;
    const int n0 = blockIdx.x * 128;
    const int warp = threadIdx.x >> 5, lane = threadIdx.x & 31;
    const int wm = warp >> 2, wn = warp & 3, g = lane >> 2, tig = lane & 3;

    float c[4][4][4];
    #pragma unroll
    for (int i = 0; i < 4; i++)
        #pragma unroll
        for (int j = 0; j < 4; j++)
            #pragma unroll
            for (int k = 0; k < 4; k++) c[i][j][k] = 0.f;

    float4 pa[4], pb[4];
    fetch_tile(input, IN_DIM, m0, 0, pa);
    fetch_tile(Wih,   IN_DIM, n0, 0, pb);

    for (int kc = 0; kc < IN_DIM; kc += 32) {
        store_tile_h(pa, As);
        store_tile_h(pb, Bs);
        __syncthreads();
        if (kc + 32 < IN_DIM) {
            fetch_tile(input, IN_DIM, m0, kc + 32, pa);
            fetch_tile(Wih,   IN_DIM, n0, kc + 32, pb);
        }
        mma_block_pre(c, As, Bs, wm, wn, g, tig);
        __syncthreads();
    }

    #pragma unroll
    for (int mi = 0; mi < 4; mi++) {
        const int row = m0 + wm * 64 + mi * 16 + g;
        #pragma unroll
        for (int ni = 0; ni < 4; ni++) {
            const int col = n0 + wn * 32 + ni * 8 + 2 * tig;
            const float b0 = bias[col], b1 = bias[col + 1];
            float2 v0 = make_float2(c[mi][ni][0] + b0, c[mi][ni][1] + b1);
            float2 v1 = make_float2(c[mi][ni][2] + b0, c[mi][ni][3] + b1);
            *reinterpret_cast<float2*>(out + (size_t)row * HID + col)       = v0;
            *reinterpret_cast<float2*>(out + (size_t)(row + 8) * HID + col) = v1;
        }
    }
}

// ---------------------------------------------------------------------------
// Group barrier: PROVEN atomic pattern, scoped to n CTAs. Graph-replay safe.
// ---------------------------------------------------------------------------
__device__ __forceinline__ void group_barrier(unsigned* bar, unsigned n) {
    unsigned* cnt   = bar;
    unsigned* phase = bar + 16;
    __threadfence();
    __syncthreads();
    if (threadIdx.x == 0) {
        const unsigned ph = *(volatile unsigned*)phase;
        if (atomicAdd(cnt, 1u) == n - 1) {
            atomicExch(cnt, 0u);
            __threadfence();
            atomicAdd(phase, 1u);
        } else {
            while (*(volatile unsigned*)phase == ph) { }
        }
        __threadfence();
    }
    __syncthreads();
}

// ---------------------------------------------------------------------------
// Recurrence: 128 CTAs = M64 x N32 tiles, FULL K=1024 (no split-K, no
// partial exchange). fp16 k16 mma; accumulators stay in registers; parity
// double-buffered g_h32; ONE scoped 32-CTA barrier per step.
// K pipeline: 4 super-phases of 8 chunks, double-buffered 8-slot halves.
// ---------------------------------------------------------------------------
__device__ __forceinline__ void issue_sp(unsigned* hb, const unsigned* ghsrc,
                                         int sp) {
    unsigned* half = hb + (sp & 1) * 8 * HCH;
    const int r = threadIdx.x >> 2, seg = (threadIdx.x & 3) * 4;
    const unsigned* rowp = ghsrc + (size_t)r * (HID / 2) + seg;
    #pragma unroll
    for (int j = 0; j < 8; j++) {
        const int kb = sp * 8 + j;
        cp_cg16(half + j * HCH + r * HROW32 + seg, rowp + kb * 16);
    }
    CP_COMMIT();
}

// warp tile m16 x n16; c[2][4]
__device__ __forceinline__ void mma_chunk(float c[2][4],
                                          const unsigned* As, const unsigned* Bs,
                                          int wm, int wn, int g, int tig) {
    #pragma unroll
    for (int ks = 0; ks < 2; ks++) {
        const int ko = ks * 8 + 2 * tig;
        const unsigned* p = As + (wm * 16 + g) * HROW32 + ko;
        uint2 alo = *reinterpret_cast<const uint2*>(p);
        uint2 ahi = *reinterpret_cast<const uint2*>(p + 8 * HROW32);
        unsigned a[4] = {alo.x, ahi.x, alo.y, ahi.y};
        #pragma unroll
        for (int ni = 0; ni < 2; ni++) {
            uint2 bb = *reinterpret_cast<const uint2*>(
                Bs + (wn * 16 + ni * 8 + g) * HROW32 + ko);
            unsigned b2[2] = {bb.x, bb.y};
            mma16(c[ni], a, b2);
        }
    }
}

__global__ void __launch_bounds__(256, 1)
recurrence_kernel(const float* __restrict__ h0, const float* __restrict__ Whh,
                  float* __restrict__ out, int write_tail) {
    extern __shared__ unsigned smem[];
    unsigned* whh  = smem;                 // 32 * WCH32 (resident fp16) = 96 KB
    unsigned* hbuf = smem + 32 * WCH32;    // 16 * HCH ring (2 halves)   = 96 KB

    const int cta = blockIdx.x;            // 0..127
    const int mt  = cta >> 5;              // 0..3  (64-row batch block)
    const int nt  = cta & 31;              // 0..31 (32-col hidden block)
    const int m0  = mt * 64;
    const int n0  = nt * 32;

    const int warp = threadIdx.x >> 5, lane = threadIdx.x & 31;
    const int wm = warp >> 1, wn = warp & 1;   // 4(m) x 2(n) warp grid
    const int g = lane >> 2, tig = lane & 3;

    unsigned* mbar = &g_mbar[mt * 32];

    // One-time: resident Whh slice [n0..n0+32) x [0..1024) -> fp16 interleaved
    #pragma unroll
    for (int kb = 0; kb < 32; kb++) {
        unsigned* ws = whh + kb * WCH32;
        int r = threadIdx.x >> 3, j = (threadIdx.x & 7) * 4;   // 256 float4s
        const float4 v = *reinterpret_cast<const float4*>(
            Whh + (size_t)(n0 + r) * HID + kb * 32 + j);
        const int grp = j >> 4, jj = j & 15;
        const int s0 = pair_slot(jj);
        unsigned* wp = ws + r * HROW32 + grp * 8;
        wp[s0]     = f2h2(v.x, v.y);
        wp[s0 + 2] = f2h2(v.z, v.w);
    }

    // Thread-owned output coords (mma accumulator layout) + fp32 h registers.
    const int r0 = m0 + wm * 16 + g;
    const int r1 = r0 + 8;
    float4 hreg[2];
    #pragma unroll
    for (int ni = 0; ni < 2; ni++) {
        const int col = n0 + wn * 16 + ni * 8 + 2 * tig;
        const float2 a0 = *reinterpret_cast<const float2*>(h0 + (size_t)r0 * HID + col);
        const float2 a1 = *reinterpret_cast<const float2*>(h0 + (size_t)r1 * HID + col);
        hreg[ni] = make_float4(a0.x, a0.y, a1.x, a1.y);
    }
    __syncthreads();   // whh resident before use

    for (int t = 0; t < T_STEPS; t++) {
        const unsigned* ghsrc = g_h32 + (size_t)(t & 1) * GH2 + (size_t)m0 * (HID / 2);

        issue_sp(hbuf, ghsrc, 0);
        issue_sp(hbuf, ghsrc, 1);

        float c[2][4];
        #pragma unroll
        for (int i = 0; i < 2; i++)
            #pragma unroll
            for (int j = 0; j < 4; j++) c[i][j] = 0.f;

#define MMA_SP(SP)                                                            \
        {                                                                     \
            unsigned* half = hbuf + ((SP) & 1) * 8 * HCH;                     \
            _Pragma("unroll")                                                 \
            for (int j = 0; j < 8; j++)                                       \
                mma_chunk(c, half + j * HCH, whh + ((SP) * 8 + j) * WCH32,    \
                          wm, wn, g, tig);                                    \
        }

        // sp=0
        asm volatile("cp.async.wait_group %0;\n" :: "n"(1));
        __syncthreads();
        MMA_SP(0)
        __syncthreads();                 // all warps done reading half 0
        issue_sp(hbuf, ghsrc, 2);        // refill half 0
        // sp=1
        asm volatile("cp.async.wait_group %0;\n" :: "n"(1));
        __syncthreads();
        MMA_SP(1)
        __syncthreads();                 // all warps done reading half 1
        issue_sp(hbuf, ghsrc, 3);        // refill half 1
        // sp=2
        asm volatile("cp.async.wait_group %0;\n" :: "n"(1));
        __syncthreads();
        MMA_SP(2)
        // sp=3
        asm volatile("cp.async.wait_group %0;\n" :: "n"(0));
        __syncthreads();
        MMA_SP(3)
#undef MMA_SP

        // ---- Thread-local epilogue: Xpre + tanh + EMA -> out, g_h[parity^1] ----
        {
            float* dst = out + (size_t)t * GH;
            unsigned* ghw = g_h32 + (size_t)((t + 1) & 1) * GH2;
            #pragma unroll
            for (int ni = 0; ni < 2; ni++) {
                const int col = n0 + wn * 16 + ni * 8 + 2 * tig;
                const float2 x0 = *reinterpret_cast<const float2*>(dst + (size_t)r0 * HID + col);
                const float2 x1 = *reinterpret_cast<const float2*>(dst + (size_t)r1 * HID + col);
                float4 r;
                r.x = fmaf(0.9f, hreg[ni].x, 0.1f * tanh_fast(c[ni][0] + x0.x));
                r.y = fmaf(0.9f, hreg[ni].y, 0.1f * tanh_fast(c[ni][1] + x0.y));
                r.z = fmaf(0.9f, hreg[ni].z, 0.1f * tanh_fast(c[ni][2] + x1.x));
                r.w = fmaf(0.9f, hreg[ni].w, 0.1f * tanh_fast(c[ni][3] + x1.y));
                hreg[ni] = r;
                *reinterpret_cast<float2*>(dst + (size_t)r0 * HID + col) = make_float2(r.x, r.y);
                *reinterpret_cast<float2*>(dst + (size_t)r1 * HID + col) = make_float2(r.z, r.w);

                const int s0 = pair_slot(col & 15);
                ghw[(size_t)r0 * (HID / 2) + (col >> 4) * 8 + s0] = f2h2(r.x, r.y);
                ghw[(size_t)r1 * (HID / 2) + (col >> 4) * 8 + s0] = f2h2(r.z, r.w);

                if (write_tail && t == T_STEPS - 1) {
                    float* tl = out + (size_t)T_STEPS * GH;
                    *reinterpret_cast<float2*>(tl + (size_t)r0 * HID + col) = make_float2(r.x, r.y);
                    *reinterpret_cast<float2*>(tl + (size_t)r1 * HID + col) = make_float2(r.z, r.w);
                }
            }
        }

        group_barrier(mbar, 32);   // mt group: h_t fully written (parity hides WAR)
    }
}

extern "C" void kernel_launch(void* const* d_in, const int* in_sizes, int n_in,
                              void* d_out, int out_size) {
    const float* input = (const float*)d_in[0];  // [512, 256, 256]
    const float* h0    = (const float*)d_in[1];  // [1, 256, 1024]
    const float* Wih   = (const float*)d_in[2];  // [1024, 256]
    const float* Whh   = (const float*)d_in[3];  // [1024, 1024]
    const float* bias  = (const float*)d_in[4];  // [1024]
    float* out = (float*)d_out;

    const int write_tail = (out_size >= T_STEPS * GH + GH) ? 1 : 0;

    static const int SMEM_BYTES = (32 * WCH32 + 16 * HCH) * 4;  // 196608
    cudaFuncSetAttribute(recurrence_kernel,
                         cudaFuncAttributeMaxDynamicSharedMemorySize, SMEM_BYTES);

    init_h_kernel<<<GH / 4 / 256, 256>>>(h0);
    precompute_kernel<<<dim3(HID / 128, (T_STEPS * BATCH) / 128), 256>>>(input, Wih, bias, out);
    recurrence_kernel<<<NCTAS, 256, SMEM_BYTES>>>(h0, Whh, out, write_tail);
}